// round 10
// baseline (speedup 1.0000x reference)
#include <cuda_runtime.h>

#define DIM_B 4096
#define DIM_M 128
#define DIM_C 128
#define DIM_Q 256
#define MT 64          // batch tile
#define NT 64          // column tile
#define KC 64          // k chunk
#define APAD 72        // floats per A smem row  (16B-aligned vector reads)
#define BPAD 68        // floats per B smem row

// ---- scratch (static device globals: no allocation allowed) ----
__device__ float g_W [DIM_Q * DIM_Q];     // combined weight (256 x 256)
__device__ float g_xsum[DIM_B * DIM_Q];   // masked row sums (4 MB)
__device__ float g_v  [DIM_B * DIM_Q];    // per-batch query vectors (4 MB)
__device__ int   g_base[DIM_B];           // exclusive prefix sum of lens
__device__ int   g_sh_len;                // 0 = int32 seq_lengths, 1 = int64

typedef unsigned long long ull;

__device__ __forceinline__ ull pack2(float lo, float hi) {
    ull r; asm("mov.b64 %0, {%1, %2};" : "=l"(r) : "f"(lo), "f"(hi)); return r;
}
__device__ __forceinline__ void unpack2(ull v, float& lo, float& hi) {
    asm("mov.b64 {%0, %1}, %2;" : "=f"(lo), "=f"(hi) : "l"(v));
}
__device__ __forceinline__ ull fma2(ull a, ull b, ull c) {
    ull d; asm("fma.rn.f32x2 %0, %1, %2, %3;" : "=l"(d) : "l"(a), "l"(b), "l"(c)); return d;
}

// ---- K0: dtype detect + exclusive prefix scan of seq_lengths ----
__global__ void scan_kernel(const int* __restrict__ seq) {
    int sh = (seq[1] == 0) ? 1 : 0;
    if (threadIdx.x == 0) g_sh_len = sh;

    __shared__ int cs[1024], cs2[1024];
    int t = threadIdx.x;              // 1024 threads, 4 lens each
    int l[4]; int sum = 0;
#pragma unroll
    for (int i = 0; i < 4; i++) {
        l[i] = seq[(size_t)(4 * t + i) << sh];
        sum += l[i];
    }
    cs[t] = sum;
    __syncthreads();
    int* src = cs; int* dst = cs2;
    for (int off = 1; off < 1024; off <<= 1) {
        int v = src[t];
        if (t >= off) v += src[t - off];
        dst[t] = v;
        __syncthreads();
        int* tmp = src; src = dst; dst = tmp;
    }
    int run = (t > 0) ? src[t - 1] : 0;   // exclusive chunk base
#pragma unroll
    for (int i = 0; i < 4; i++) {
        g_base[4 * t + i] = run;
        run += l[i];
    }
}

// ---- K0a: fused W = (Wk^T Wc^T) @ proj. Block q computes row W[q][:]. ----
__global__ void wcomb_kernel(const float* __restrict__ Wk, const float* __restrict__ Wc,
                             const float* __restrict__ proj) {
    __shared__ float t1[DIM_M];       // T1[q][m] for this q
    int q = blockIdx.x;               // 0..255
    int t = threadIdx.x;              // 0..127
    float s = 0.f;
#pragma unroll 4
    for (int c = 0; c < DIM_C; c++)
        s = fmaf(Wk[c * DIM_Q + q], Wc[t * DIM_C + c], s);
    t1[t] = s;
    __syncthreads();
    float s0 = 0.f, s1 = 0.f;
#pragma unroll 4
    for (int m = 0; m < DIM_M; m++) {
        float a = t1[m];
        s0 = fmaf(a, proj[m * DIM_Q + t], s0);
        s1 = fmaf(a, proj[m * DIM_Q + 128 + t], s1);
    }
    g_W[q * DIM_Q + t]       = s0;
    g_W[q * DIM_Q + 128 + t] = s1;
}

// ---- K1: xsum[b][q] = sum_{m < len[b]} xss[b][m][q]  (block per batch) ----
__global__ void xsum_kernel(const float* __restrict__ xss, const int* __restrict__ seq) {
    int b   = blockIdx.x;
    int len = seq[(size_t)b << g_sh_len];
    int t   = threadIdx.x;           // 256 threads
    int q4  = t & 63;                // float4 column
    int mg  = t >> 6;                // row group 0..3
    const float4* base = (const float4*)xss + (size_t)b * (DIM_M * DIM_Q / 4);
    float4 acc = make_float4(0.f, 0.f, 0.f, 0.f);
#pragma unroll 4
    for (int m = mg; m < len; m += 4) {
        float4 v = base[m * (DIM_Q / 4) + q4];
        acc.x += v.x; acc.y += v.y; acc.z += v.z; acc.w += v.w;
    }
    __shared__ float4 red[4][64];
    red[mg][q4] = acc;
    __syncthreads();
    if (t < 64) {
        float4 a = red[0][t], c = red[1][t], d = red[2][t], e = red[3][t];
        float4 s;
        s.x = (a.x + c.x) + (d.x + e.x);
        s.y = (a.y + c.y) + (d.y + e.y);
        s.z = (a.z + c.z) + (d.z + e.z);
        s.w = (a.w + c.w) + (d.w + e.w);
        ((float4*)(g_xsum + (size_t)b * DIM_Q))[t] = s;
    }
}

// ---- K2: v = xsum @ W as a smem-tiled GEMM (unchanged from R9, 24.7us). ----
__global__ void __launch_bounds__(256) vgemm_kernel() {
    __shared__ float sA[KC * APAD];     // [k][m], 18.4 KB
    __shared__ float sB[KC * BPAD];     // [k][n], 17.4 KB

    int t  = threadIdx.x;               // 0..255
    int mt = (blockIdx.x >> 2) * MT;    // batch-tile base (adjacent blocks share it)
    int nt = (blockIdx.x & 3) * NT;     // column-tile base
    int iq = t >> 4;                    // batch quad 0..15 -> batches mt+4iq..+3
    int jq = t & 15;                    // col  quad 0..15 -> cols nt+4jq..+3

    unsigned aaddr0 = (unsigned)__cvta_generic_to_shared(sA) + 16u * (unsigned)iq;
    unsigned baddr0 = (unsigned)__cvta_generic_to_shared(sB) + 16u * (unsigned)jq;

    ull a00 = 0ull, a01 = 0ull, a02 = 0ull, a03 = 0ull;  // pair (4iq,4iq+1) x col 0..3
    ull a10 = 0ull, a11 = 0ull, a12 = 0ull, a13 = 0ull;  // pair (4iq+2,4iq+3)

    int sm = t >> 6;                    // A staging: row group 0..3
    int sk = t & 63;                    //            k within chunk
    int bk = t >> 4;                    // B staging: k row group (16 rows/pass)

    for (int kc = 0; kc < DIM_Q; kc += KC) {
        if (kc) __syncthreads();
        // stage A transposed: sA[k][m] = xsum[mt+m][kc+k]
#pragma unroll
        for (int p = 0; p < 16; p++) {
            int m = sm + 4 * p;
            sA[sk * APAD + m] = g_xsum[(size_t)(mt + m) * DIM_Q + kc + sk];
        }
        // stage B: sB[k][n] = W[kc+k][nt+n]
#pragma unroll
        for (int p = 0; p < 4; p++) {
            int k = bk + 16 * p;
            ((float4*)&sB[k * BPAD])[jq] =
                ((const float4*)&g_W[(kc + k) * DIM_Q + nt])[jq];
        }
        __syncthreads();

        unsigned aaddr = aaddr0, baddr = baddr0;
#pragma unroll 8
        for (int k = 0; k < KC; k++) {
            ull x0, x1;
            asm volatile("ld.shared.v2.u64 {%0,%1}, [%2];"
                         : "=l"(x0), "=l"(x1) : "r"(aaddr));
            float4 wv;
            asm volatile("ld.shared.v4.f32 {%0,%1,%2,%3}, [%4];"
                         : "=f"(wv.x), "=f"(wv.y), "=f"(wv.z), "=f"(wv.w) : "r"(baddr));
            ull w0 = pack2(wv.x, wv.x);
            ull w1 = pack2(wv.y, wv.y);
            ull w2 = pack2(wv.z, wv.z);
            ull w3 = pack2(wv.w, wv.w);
            a00 = fma2(x0, w0, a00);  a10 = fma2(x1, w0, a10);
            a01 = fma2(x0, w1, a01);  a11 = fma2(x1, w1, a11);
            a02 = fma2(x0, w2, a02);  a12 = fma2(x1, w2, a12);
            a03 = fma2(x0, w3, a03);  a13 = fma2(x1, w3, a13);
            aaddr += APAD * 4u;
            baddr += BPAD * 4u;
        }
    }

    // write 4x4 outputs: v[mt+4iq+r][nt+4jq..+3], float4 per batch (coalesced in jq)
    int b0 = mt + 4 * iq;
    int cq = (nt >> 2) + jq;            // float4 column index
    float4 o; float lo, hi, h0, h1, h2, h3;
    unpack2(a00, lo, hi); o.x = lo; h0 = hi;
    unpack2(a01, lo, hi); o.y = lo; h1 = hi;
    unpack2(a02, lo, hi); o.z = lo; h2 = hi;
    unpack2(a03, lo, hi); o.w = lo; h3 = hi;
    ((float4*)(g_v + (size_t)(b0 + 0) * DIM_Q))[cq] = o;
    o.x = h0; o.y = h1; o.z = h2; o.w = h3;
    ((float4*)(g_v + (size_t)(b0 + 1) * DIM_Q))[cq] = o;
    unpack2(a10, lo, hi); o.x = lo; h0 = hi;
    unpack2(a11, lo, hi); o.y = lo; h1 = hi;
    unpack2(a12, lo, hi); o.z = lo; h2 = hi;
    unpack2(a13, lo, hi); o.w = lo; h3 = hi;
    ((float4*)(g_v + (size_t)(b0 + 2) * DIM_Q))[cq] = o;
    o.x = h0; o.y = h1; o.z = h2; o.w = h3;
    ((float4*)(g_v + (size_t)(b0 + 3) * DIM_Q))[cq] = o;
}

// ---- K3: y, shuffle-free. Lane l: row 4g+(l>>3), col quad (l&7).
// Per iter: 8 independent LDG.128 + 32 FMA (2 chains) + 1 STS. No reduction
// in the load stream; final 8-way sums via smem after one barrier. ----
__global__ void y_kernel(const float* __restrict__ xss, const int* __restrict__ seq,
                         float* __restrict__ out) {
    __shared__ float partial[DIM_M][9];   // 9-float rows: conflict-free phase 2
    int b    = (DIM_B - 1) - blockIdx.x;  // reversed: L2 tail reuse from xsum
    int len  = seq[(size_t)b << g_sh_len];
    int base = g_base[b];
    int t    = threadIdx.x;               // 256
    int w    = t >> 5, lane = t & 31;
    int sub  = lane >> 3;                 // row within group of 4
    int quad = lane & 7;                  // base column quad

    const float4* vr = (const float4*)(g_v + (size_t)b * DIM_Q);
    float4 vq[8];
#pragma unroll
    for (int cc = 0; cc < 8; cc++) vq[cc] = vr[quad + 8 * cc];

    const float4* xb = (const float4*)(xss + (size_t)b * DIM_M * DIM_Q);

    for (int g = w; 4 * g < len; g += 8) {
        int row = 4 * g + sub;
        const float4* xr = xb + (size_t)row * 64 + quad;
        float4 x0 = xr[0],  x1 = xr[8],  x2 = xr[16], x3 = xr[24];
        float4 x4 = xr[32], x5 = xr[40], x6 = xr[48], x7 = xr[56];
        float s0 = 0.f, s1 = 0.f;
        s0 = fmaf(x0.x, vq[0].x, s0); s0 = fmaf(x0.y, vq[0].y, s0);
        s0 = fmaf(x0.z, vq[0].z, s0); s0 = fmaf(x0.w, vq[0].w, s0);
        s1 = fmaf(x1.x, vq[1].x, s1); s1 = fmaf(x1.y, vq[1].y, s1);
        s1 = fmaf(x1.z, vq[1].z, s1); s1 = fmaf(x1.w, vq[1].w, s1);
        s0 = fmaf(x2.x, vq[2].x, s0); s0 = fmaf(x2.y, vq[2].y, s0);
        s0 = fmaf(x2.z, vq[2].z, s0); s0 = fmaf(x2.w, vq[2].w, s0);
        s1 = fmaf(x3.x, vq[3].x, s1); s1 = fmaf(x3.y, vq[3].y, s1);
        s1 = fmaf(x3.z, vq[3].z, s1); s1 = fmaf(x3.w, vq[3].w, s1);
        s0 = fmaf(x4.x, vq[4].x, s0); s0 = fmaf(x4.y, vq[4].y, s0);
        s0 = fmaf(x4.z, vq[4].z, s0); s0 = fmaf(x4.w, vq[4].w, s0);
        s1 = fmaf(x5.x, vq[5].x, s1); s1 = fmaf(x5.y, vq[5].y, s1);
        s1 = fmaf(x5.z, vq[5].z, s1); s1 = fmaf(x5.w, vq[5].w, s1);
        s0 = fmaf(x6.x, vq[6].x, s0); s0 = fmaf(x6.y, vq[6].y, s0);
        s0 = fmaf(x6.z, vq[6].z, s0); s0 = fmaf(x6.w, vq[6].w, s0);
        s1 = fmaf(x7.x, vq[7].x, s1); s1 = fmaf(x7.y, vq[7].y, s1);
        s1 = fmaf(x7.z, vq[7].z, s1); s1 = fmaf(x7.w, vq[7].w, s1);
        partial[row][quad] = s0 + s1;
    }
    __syncthreads();

    if (t < DIM_M && t < len) {
        float* p = partial[t];
        float r = ((p[0] + p[1]) + (p[2] + p[3])) + ((p[4] + p[5]) + (p[6] + p[7]));
        out[base + t] = r;
    }
}

extern "C" void kernel_launch(void* const* d_in, const int* in_sizes, int n_in,
                              void* d_out, int out_size) {
    const float* xss  = (const float*)d_in[0];
    const float* Wk   = (const float*)d_in[1];
    const float* Wc   = (const float*)d_in[2];
    const float* proj = (const float*)d_in[3];
    const int*   seq  = (const int*)d_in[4];
    float* out = (float*)d_out;

    scan_kernel<<<1, 1024>>>(seq);
    wcomb_kernel<<<DIM_Q, DIM_C>>>(Wk, Wc, proj);
    xsum_kernel<<<DIM_B, 256>>>(xss, seq);
    vgemm_kernel<<<256, 256>>>();
    y_kernel<<<DIM_B, 256>>>(xss, seq, out);
}

// round 16
// speedup vs baseline: 1.0924x; 1.0924x over previous
#include <cuda_runtime.h>

#define DIM_B 4096
#define DIM_M 128
#define DIM_C 128
#define DIM_Q 256
#define MT 128         // batch tile
#define NT 64          // column tile
#define KC 64          // k chunk
#define APAD 132       // floats per A smem row (16B-aligned, 4-way STS conflicts)
#define BPAD 68        // floats per B smem row

// ---- scratch (static device globals: no allocation allowed) ----
__device__ float g_W [DIM_Q * DIM_Q];     // combined weight (256 x 256)
__device__ float g_xsum[DIM_B * DIM_Q];   // masked row sums (4 MB)
__device__ float g_v  [DIM_B * DIM_Q];    // per-batch query vectors (4 MB)
__device__ int   g_base[DIM_B];           // exclusive prefix sum of lens
__device__ int   g_sh_len;                // 0 = int32 seq_lengths, 1 = int64

typedef unsigned long long ull;

__device__ __forceinline__ ull pack2(float lo, float hi) {
    ull r; asm("mov.b64 %0, {%1, %2};" : "=l"(r) : "f"(lo), "f"(hi)); return r;
}
__device__ __forceinline__ void unpack2(ull v, float& lo, float& hi) {
    asm("mov.b64 {%0, %1}, %2;" : "=f"(lo), "=f"(hi) : "l"(v));
}
__device__ __forceinline__ ull fma2(ull a, ull b, ull c) {
    ull d; asm("fma.rn.f32x2 %0, %1, %2, %3;" : "=l"(d) : "l"(a), "l"(b), "l"(c)); return d;
}

// ---- K0: dtype detect + exclusive prefix scan of seq_lengths ----
__global__ void scan_kernel(const int* __restrict__ seq) {
    int sh = (seq[1] == 0) ? 1 : 0;
    if (threadIdx.x == 0) g_sh_len = sh;

    __shared__ int cs[1024], cs2[1024];
    int t = threadIdx.x;              // 1024 threads, 4 lens each
    int l[4]; int sum = 0;
#pragma unroll
    for (int i = 0; i < 4; i++) {
        l[i] = seq[(size_t)(4 * t + i) << sh];
        sum += l[i];
    }
    cs[t] = sum;
    __syncthreads();
    int* src = cs; int* dst = cs2;
    for (int off = 1; off < 1024; off <<= 1) {
        int v = src[t];
        if (t >= off) v += src[t - off];
        dst[t] = v;
        __syncthreads();
        int* tmp = src; src = dst; dst = tmp;
    }
    int run = (t > 0) ? src[t - 1] : 0;   // exclusive chunk base
#pragma unroll
    for (int i = 0; i < 4; i++) {
        g_base[4 * t + i] = run;
        run += l[i];
    }
}

// ---- K0a: fused W = (Wk^T Wc^T) @ proj. Block q computes row W[q][:]. ----
__global__ void wcomb_kernel(const float* __restrict__ Wk, const float* __restrict__ Wc,
                             const float* __restrict__ proj) {
    __shared__ float t1[DIM_M];       // T1[q][m] for this q
    int q = blockIdx.x;               // 0..255
    int t = threadIdx.x;              // 0..127
    float s = 0.f;
#pragma unroll 4
    for (int c = 0; c < DIM_C; c++)
        s = fmaf(Wk[c * DIM_Q + q], Wc[t * DIM_C + c], s);
    t1[t] = s;
    __syncthreads();
    float s0 = 0.f, s1 = 0.f;
#pragma unroll 4
    for (int m = 0; m < DIM_M; m++) {
        float a = t1[m];
        s0 = fmaf(a, proj[m * DIM_Q + t], s0);
        s1 = fmaf(a, proj[m * DIM_Q + 128 + t], s1);
    }
    g_W[q * DIM_Q + t]       = s0;
    g_W[q * DIM_Q + 128 + t] = s1;
}

// ---- K1: xsum[b][q] = sum_{m < len[b]} xss[b][m][q]  (block per batch) ----
__global__ void xsum_kernel(const float* __restrict__ xss, const int* __restrict__ seq) {
    int b   = blockIdx.x;
    int len = seq[(size_t)b << g_sh_len];
    int t   = threadIdx.x;           // 256 threads
    int q4  = t & 63;                // float4 column
    int mg  = t >> 6;                // row group 0..3
    const float4* base = (const float4*)xss + (size_t)b * (DIM_M * DIM_Q / 4);
    float4 acc = make_float4(0.f, 0.f, 0.f, 0.f);
#pragma unroll 4
    for (int m = mg; m < len; m += 4) {
        float4 v = base[m * (DIM_Q / 4) + q4];
        acc.x += v.x; acc.y += v.y; acc.z += v.z; acc.w += v.w;
    }
    __shared__ float4 red[4][64];
    red[mg][q4] = acc;
    __syncthreads();
    if (t < 64) {
        float4 a = red[0][t], c = red[1][t], d = red[2][t], e = red[3][t];
        float4 s;
        s.x = (a.x + c.x) + (d.x + e.x);
        s.y = (a.y + c.y) + (d.y + e.y);
        s.z = (a.z + c.z) + (d.z + e.z);
        s.w = (a.w + c.w) + (d.w + e.w);
        ((float4*)(g_xsum + (size_t)b * DIM_Q))[t] = s;
    }
}

// ---- K2: v = xsum @ W as a smem-tiled GEMM.
// 128 blocks (32 M-tiles x 4 N-tiles) x 512 threads: single wave, 16 warps/SM.
// Thread = 4 batches x 4 cols; inner loop pure LDS + FFMA2 (same shape as R9).
__global__ void __launch_bounds__(512) vgemm_kernel() {
    __shared__ float sA[KC * APAD];     // [k][m], 33.8 KB
    __shared__ float sB[KC * BPAD];     // [k][n], 17.4 KB

    int t  = threadIdx.x;               // 0..511
    int mt = (blockIdx.x >> 2) * MT;    // batch-tile base
    int nt = (blockIdx.x & 3) * NT;     // column-tile base
    int iq = t >> 4;                    // batch quad 0..31 -> batches mt+4iq..+3
    int jq = t & 15;                    // col  quad 0..15 -> cols nt+4jq..+3

    unsigned aaddr0 = (unsigned)__cvta_generic_to_shared(sA) + 16u * (unsigned)iq;
    unsigned baddr0 = (unsigned)__cvta_generic_to_shared(sB) + 16u * (unsigned)jq;

    ull a00 = 0ull, a01 = 0ull, a02 = 0ull, a03 = 0ull;  // pair (4iq,4iq+1) x col 0..3
    ull a10 = 0ull, a11 = 0ull, a12 = 0ull, a13 = 0ull;  // pair (4iq+2,4iq+3)

    int sm = t >> 6;                    // A staging: m group 0..7
    int sk = t & 63;                    //            k within chunk
    int bk = t >> 4;                    // B staging: k row group (32 rows/pass)

    for (int kc = 0; kc < DIM_Q; kc += KC) {
        if (kc) __syncthreads();
        // stage A transposed: sA[k][m] = xsum[mt+m][kc+k]
#pragma unroll
        for (int p = 0; p < 16; p++) {
            int m = sm + 8 * p;
            sA[sk * APAD + m] = g_xsum[(size_t)(mt + m) * DIM_Q + kc + sk];
        }
        // stage B: sB[k][n] = W[kc+k][nt+n]
#pragma unroll
        for (int p = 0; p < 2; p++) {
            int k = bk + 32 * p;
            ((float4*)&sB[k * BPAD])[jq] =
                ((const float4*)&g_W[(kc + k) * DIM_Q + nt])[jq];
        }
        __syncthreads();

        unsigned aaddr = aaddr0, baddr = baddr0;
#pragma unroll 8
        for (int k = 0; k < KC; k++) {
            ull x0, x1;
            asm volatile("ld.shared.v2.u64 {%0,%1}, [%2];"
                         : "=l"(x0), "=l"(x1) : "r"(aaddr));
            float4 wv;
            asm volatile("ld.shared.v4.f32 {%0,%1,%2,%3}, [%4];"
                         : "=f"(wv.x), "=f"(wv.y), "=f"(wv.z), "=f"(wv.w) : "r"(baddr));
            ull w0 = pack2(wv.x, wv.x);
            ull w1 = pack2(wv.y, wv.y);
            ull w2 = pack2(wv.z, wv.z);
            ull w3 = pack2(wv.w, wv.w);
            a00 = fma2(x0, w0, a00);  a10 = fma2(x1, w0, a10);
            a01 = fma2(x0, w1, a01);  a11 = fma2(x1, w1, a11);
            a02 = fma2(x0, w2, a02);  a12 = fma2(x1, w2, a12);
            a03 = fma2(x0, w3, a03);  a13 = fma2(x1, w3, a13);
            aaddr += APAD * 4u;
            baddr += BPAD * 4u;
        }
    }

    // write 4x4 outputs: v[mt+4iq+r][nt+4jq..+3], float4 per batch (coalesced in jq)
    int b0 = mt + 4 * iq;
    int cq = (nt >> 2) + jq;            // float4 column index
    float4 o; float lo, hi, h0, h1, h2, h3;
    unpack2(a00, lo, hi); o.x = lo; h0 = hi;
    unpack2(a01, lo, hi); o.y = lo; h1 = hi;
    unpack2(a02, lo, hi); o.z = lo; h2 = hi;
    unpack2(a03, lo, hi); o.w = lo; h3 = hi;
    ((float4*)(g_v + (size_t)(b0 + 0) * DIM_Q))[cq] = o;
    o.x = h0; o.y = h1; o.z = h2; o.w = h3;
    ((float4*)(g_v + (size_t)(b0 + 1) * DIM_Q))[cq] = o;
    unpack2(a10, lo, hi); o.x = lo; h0 = hi;
    unpack2(a11, lo, hi); o.y = lo; h1 = hi;
    unpack2(a12, lo, hi); o.z = lo; h2 = hi;
    unpack2(a13, lo, hi); o.w = lo; h3 = hi;
    ((float4*)(g_v + (size_t)(b0 + 2) * DIM_Q))[cq] = o;
    o.x = h0; o.y = h1; o.z = h2; o.w = h3;
    ((float4*)(g_v + (size_t)(b0 + 3) * DIM_Q))[cq] = o;
}

// ---- K3: y, block-per-batch, reversed order (L2 tail reuse), 2-row ILP ----
__global__ void y_kernel(const float* __restrict__ xss, const int* __restrict__ seq,
                         float* __restrict__ out) {
    int b    = (DIM_B - 1) - blockIdx.x;
    int len  = seq[(size_t)b << g_sh_len];
    int base = g_base[b];
    int t    = threadIdx.x;          // 256
    int w    = t >> 5, lane = t & 31;

    const float4* vr = (const float4*)(g_v + (size_t)b * DIM_Q);
    float4 v0 = vr[lane];
    float4 v1 = vr[lane + 32];

    const float4* xb = (const float4*)(xss + (size_t)b * DIM_M * DIM_Q);

    int m = w;
    for (; m + 8 < len; m += 16) {
        float4 a0 = xb[(size_t)m * 64 + lane];
        float4 a1 = xb[(size_t)m * 64 + 32 + lane];
        float4 c0 = xb[(size_t)(m + 8) * 64 + lane];
        float4 c1 = xb[(size_t)(m + 8) * 64 + 32 + lane];
        float s0 = 0.f, s1 = 0.f;
        s0 = fmaf(a0.x, v0.x, s0); s0 = fmaf(a0.y, v0.y, s0);
        s0 = fmaf(a0.z, v0.z, s0); s0 = fmaf(a0.w, v0.w, s0);
        s0 = fmaf(a1.x, v1.x, s0); s0 = fmaf(a1.y, v1.y, s0);
        s0 = fmaf(a1.z, v1.z, s0); s0 = fmaf(a1.w, v1.w, s0);
        s1 = fmaf(c0.x, v0.x, s1); s1 = fmaf(c0.y, v0.y, s1);
        s1 = fmaf(c0.z, v0.z, s1); s1 = fmaf(c0.w, v0.w, s1);
        s1 = fmaf(c1.x, v1.x, s1); s1 = fmaf(c1.y, v1.y, s1);
        s1 = fmaf(c1.z, v1.z, s1); s1 = fmaf(c1.w, v1.w, s1);
#pragma unroll
        for (int off = 16; off > 0; off >>= 1) {
            s0 += __shfl_xor_sync(0xffffffffu, s0, off);
            s1 += __shfl_xor_sync(0xffffffffu, s1, off);
        }
        if (lane == 0) {
            out[base + m]     = s0;
            out[base + m + 8] = s1;
        }
    }
    if (m < len) {
        float4 a0 = xb[(size_t)m * 64 + lane];
        float4 a1 = xb[(size_t)m * 64 + 32 + lane];
        float s0 = 0.f;
        s0 = fmaf(a0.x, v0.x, s0); s0 = fmaf(a0.y, v0.y, s0);
        s0 = fmaf(a0.z, v0.z, s0); s0 = fmaf(a0.w, v0.w, s0);
        s0 = fmaf(a1.x, v1.x, s0); s0 = fmaf(a1.y, v1.y, s0);
        s0 = fmaf(a1.z, v1.z, s0); s0 = fmaf(a1.w, v1.w, s0);
#pragma unroll
        for (int off = 16; off > 0; off >>= 1)
            s0 += __shfl_xor_sync(0xffffffffu, s0, off);
        if (lane == 0) out[base + m] = s0;
    }
}

extern "C" void kernel_launch(void* const* d_in, const int* in_sizes, int n_in,
                              void* d_out, int out_size) {
    const float* xss  = (const float*)d_in[0];
    const float* Wk   = (const float*)d_in[1];
    const float* Wc   = (const float*)d_in[2];
    const float* proj = (const float*)d_in[3];
    const int*   seq  = (const int*)d_in[4];
    float* out = (float*)d_out;

    scan_kernel<<<1, 1024>>>(seq);
    wcomb_kernel<<<DIM_Q, DIM_C>>>(Wk, Wc, proj);
    xsum_kernel<<<DIM_B, 256>>>(xss, seq);
    vgemm_kernel<<<128, 512>>>();
    y_kernel<<<DIM_B, 256>>>(xss, seq, out);
}

// round 17
// speedup vs baseline: 1.1604x; 1.0622x over previous
#include <cuda_runtime.h>

#define DIM_B 4096
#define DIM_M 128
#define DIM_C 128
#define DIM_Q 256
#define MT 128         // batch tile
#define NT 64          // column tile
#define KC 64          // k chunk
#define APAD 132       // floats per A smem row (16B-aligned, 4-way STS conflicts)
#define BPAD 68        // floats per B smem row

// ---- scratch (static device globals: no allocation allowed) ----
__device__ float g_W [DIM_Q * DIM_Q];     // combined weight (256 x 256)
__device__ float g_xsum[DIM_B * DIM_Q];   // masked row sums (4 MB)
__device__ float g_v  [DIM_B * DIM_Q];    // per-batch query vectors (4 MB)
__device__ int   g_base[DIM_B];           // exclusive prefix sum of lens

typedef unsigned long long ull;

__device__ __forceinline__ ull pack2(float lo, float hi) {
    ull r; asm("mov.b64 %0, {%1, %2};" : "=l"(r) : "f"(lo), "f"(hi)); return r;
}
__device__ __forceinline__ void unpack2(ull v, float& lo, float& hi) {
    asm("mov.b64 {%0, %1}, %2;" : "=f"(lo), "=f"(hi) : "l"(v));
}
__device__ __forceinline__ ull fma2(ull a, ull b, ull c) {
    ull d; asm("fma.rn.f32x2 %0, %1, %2, %3;" : "=l"(d) : "l"(a), "l"(b), "l"(c)); return d;
}

// int32 vs int64 detect, inline: lens[1]=38, gidx[1]=128 -> word[1]!=0 iff int32.
__device__ __forceinline__ int seq_shift(const int* seq) {
    return (seq[1] == 0) ? 1 : 0;
}

// ---- K0: fused setup. Blocks 0..255: W row q. Block 256: prefix scan of lens. ----
__global__ void setup_kernel(const float* __restrict__ Wk, const float* __restrict__ Wc,
                             const float* __restrict__ proj, const int* __restrict__ seq) {
    int t = threadIdx.x;                  // 0..255
    if (blockIdx.x == DIM_Q) {
        // exclusive prefix scan of 4096 lens: 256 threads x 16 each
        int sh = seq_shift(seq);
        __shared__ int cs[256], cs2[256];
        int l[16]; int sum = 0;
#pragma unroll
        for (int i = 0; i < 16; i++) {
            l[i] = seq[(size_t)(16 * t + i) << sh];
            sum += l[i];
        }
        cs[t] = sum;
        __syncthreads();
        int* src = cs; int* dst = cs2;
        for (int off = 1; off < 256; off <<= 1) {
            int v = src[t];
            if (t >= off) v += src[t - off];
            dst[t] = v;
            __syncthreads();
            int* tmp = src; src = dst; dst = tmp;
        }
        int run = (t > 0) ? src[t - 1] : 0;
#pragma unroll
        for (int i = 0; i < 16; i++) {
            g_base[16 * t + i] = run;
            run += l[i];
        }
        return;
    }
    // W[q][t] = sum_m (sum_c Wk[c][q] Wc[m][c]) proj[m][t]
    __shared__ float t1[DIM_M];
    int q = blockIdx.x;
    if (t < DIM_M) {
        float s = 0.f;
#pragma unroll 4
        for (int c = 0; c < DIM_C; c++)
            s = fmaf(Wk[c * DIM_Q + q], Wc[t * DIM_C + c], s);
        t1[t] = s;
    }
    __syncthreads();
    float s0 = 0.f;
#pragma unroll 4
    for (int m = 0; m < DIM_M; m++)
        s0 = fmaf(t1[m], proj[m * DIM_Q + t], s0);
    g_W[q * DIM_Q + t] = s0;
}

// ---- K1: xsum[b][q] = sum_{m < len[b]} xss[b][m][q]  (block per batch) ----
__global__ void xsum_kernel(const float* __restrict__ xss, const int* __restrict__ seq) {
    int sh  = seq_shift(seq);
    int b   = blockIdx.x;
    int len = seq[(size_t)b << sh];
    int t   = threadIdx.x;           // 256 threads
    int q4  = t & 63;                // float4 column
    int mg  = t >> 6;                // row group 0..3
    const float4* base = (const float4*)xss + (size_t)b * (DIM_M * DIM_Q / 4);
    float4 acc = make_float4(0.f, 0.f, 0.f, 0.f);
#pragma unroll 4
    for (int m = mg; m < len; m += 4) {
        float4 v = base[m * (DIM_Q / 4) + q4];
        acc.x += v.x; acc.y += v.y; acc.z += v.z; acc.w += v.w;
    }
    __shared__ float4 red[4][64];
    red[mg][q4] = acc;
    __syncthreads();
    if (t < 64) {
        float4 a = red[0][t], c = red[1][t], d = red[2][t], e = red[3][t];
        float4 s;
        s.x = (a.x + c.x) + (d.x + e.x);
        s.y = (a.y + c.y) + (d.y + e.y);
        s.z = (a.z + c.z) + (d.z + e.z);
        s.w = (a.w + c.w) + (d.w + e.w);
        ((float4*)(g_xsum + (size_t)b * DIM_Q))[t] = s;
    }
}

// ---- K2: v = xsum @ W as a smem-tiled GEMM (unchanged, 22.1us). ----
__global__ void __launch_bounds__(512) vgemm_kernel() {
    __shared__ float sA[KC * APAD];     // [k][m], 33.8 KB
    __shared__ float sB[KC * BPAD];     // [k][n], 17.4 KB

    int t  = threadIdx.x;               // 0..511
    int mt = (blockIdx.x >> 2) * MT;    // batch-tile base
    int nt = (blockIdx.x & 3) * NT;     // column-tile base
    int iq = t >> 4;                    // batch quad 0..31 -> batches mt+4iq..+3
    int jq = t & 15;                    // col  quad 0..15 -> cols nt+4jq..+3

    unsigned aaddr0 = (unsigned)__cvta_generic_to_shared(sA) + 16u * (unsigned)iq;
    unsigned baddr0 = (unsigned)__cvta_generic_to_shared(sB) + 16u * (unsigned)jq;

    ull a00 = 0ull, a01 = 0ull, a02 = 0ull, a03 = 0ull;  // pair (4iq,4iq+1) x col 0..3
    ull a10 = 0ull, a11 = 0ull, a12 = 0ull, a13 = 0ull;  // pair (4iq+2,4iq+3)

    int sm = t >> 6;                    // A staging: m group 0..7
    int sk = t & 63;                    //            k within chunk
    int bk = t >> 4;                    // B staging: k row group (32 rows/pass)

    for (int kc = 0; kc < DIM_Q; kc += KC) {
        if (kc) __syncthreads();
        // stage A transposed: sA[k][m] = xsum[mt+m][kc+k]
#pragma unroll
        for (int p = 0; p < 16; p++) {
            int m = sm + 8 * p;
            sA[sk * APAD + m] = g_xsum[(size_t)(mt + m) * DIM_Q + kc + sk];
        }
        // stage B: sB[k][n] = W[kc+k][nt+n]
#pragma unroll
        for (int p = 0; p < 2; p++) {
            int k = bk + 32 * p;
            ((float4*)&sB[k * BPAD])[jq] =
                ((const float4*)&g_W[(kc + k) * DIM_Q + nt])[jq];
        }
        __syncthreads();

        unsigned aaddr = aaddr0, baddr = baddr0;
#pragma unroll 8
        for (int k = 0; k < KC; k++) {
            ull x0, x1;
            asm volatile("ld.shared.v2.u64 {%0,%1}, [%2];"
                         : "=l"(x0), "=l"(x1) : "r"(aaddr));
            float4 wv;
            asm volatile("ld.shared.v4.f32 {%0,%1,%2,%3}, [%4];"
                         : "=f"(wv.x), "=f"(wv.y), "=f"(wv.z), "=f"(wv.w) : "r"(baddr));
            ull w0 = pack2(wv.x, wv.x);
            ull w1 = pack2(wv.y, wv.y);
            ull w2 = pack2(wv.z, wv.z);
            ull w3 = pack2(wv.w, wv.w);
            a00 = fma2(x0, w0, a00);  a10 = fma2(x1, w0, a10);
            a01 = fma2(x0, w1, a01);  a11 = fma2(x1, w1, a11);
            a02 = fma2(x0, w2, a02);  a12 = fma2(x1, w2, a12);
            a03 = fma2(x0, w3, a03);  a13 = fma2(x1, w3, a13);
            aaddr += APAD * 4u;
            baddr += BPAD * 4u;
        }
    }

    // write 4x4 outputs: v[mt+4iq+r][nt+4jq..+3], float4 per batch (coalesced in jq)
    int b0 = mt + 4 * iq;
    int cq = (nt >> 2) + jq;            // float4 column index
    float4 o; float lo, hi, h0, h1, h2, h3;
    unpack2(a00, lo, hi); o.x = lo; h0 = hi;
    unpack2(a01, lo, hi); o.y = lo; h1 = hi;
    unpack2(a02, lo, hi); o.z = lo; h2 = hi;
    unpack2(a03, lo, hi); o.w = lo; h3 = hi;
    ((float4*)(g_v + (size_t)(b0 + 0) * DIM_Q))[cq] = o;
    o.x = h0; o.y = h1; o.z = h2; o.w = h3;
    ((float4*)(g_v + (size_t)(b0 + 1) * DIM_Q))[cq] = o;
    unpack2(a10, lo, hi); o.x = lo; h0 = hi;
    unpack2(a11, lo, hi); o.y = lo; h1 = hi;
    unpack2(a12, lo, hi); o.z = lo; h2 = hi;
    unpack2(a13, lo, hi); o.w = lo; h3 = hi;
    ((float4*)(g_v + (size_t)(b0 + 2) * DIM_Q))[cq] = o;
    o.x = h0; o.y = h1; o.z = h2; o.w = h3;
    ((float4*)(g_v + (size_t)(b0 + 3) * DIM_Q))[cq] = o;
}

// ---- K3: y. 2 blocks per batch (64-row halves), reversed batch order,
// 2-row ILP. Halved critical path smooths ragged stragglers. ----
__global__ void y_kernel(const float* __restrict__ xss, const int* __restrict__ seq,
                         float* __restrict__ out) {
    int sh   = seq_shift(seq);
    int half = blockIdx.x & 1;
    int b    = (DIM_B - 1) - (blockIdx.x >> 1);
    int len  = seq[(size_t)b << sh];
    int m0   = half * 64;
    if (m0 >= len) return;
    int mend = (len < m0 + 64) ? len : (m0 + 64);
    int base = g_base[b];
    int t    = threadIdx.x;          // 256
    int w    = t >> 5, lane = t & 31;

    const float4* vr = (const float4*)(g_v + (size_t)b * DIM_Q);
    float4 v0 = vr[lane];
    float4 v1 = vr[lane + 32];

    const float4* xb = (const float4*)(xss + (size_t)b * DIM_M * DIM_Q);

    int m = m0 + w;
    for (; m + 8 < mend; m += 16) {
        float4 a0 = xb[(size_t)m * 64 + lane];
        float4 a1 = xb[(size_t)m * 64 + 32 + lane];
        float4 c0 = xb[(size_t)(m + 8) * 64 + lane];
        float4 c1 = xb[(size_t)(m + 8) * 64 + 32 + lane];
        float s0 = 0.f, s1 = 0.f;
        s0 = fmaf(a0.x, v0.x, s0); s0 = fmaf(a0.y, v0.y, s0);
        s0 = fmaf(a0.z, v0.z, s0); s0 = fmaf(a0.w, v0.w, s0);
        s0 = fmaf(a1.x, v1.x, s0); s0 = fmaf(a1.y, v1.y, s0);
        s0 = fmaf(a1.z, v1.z, s0); s0 = fmaf(a1.w, v1.w, s0);
        s1 = fmaf(c0.x, v0.x, s1); s1 = fmaf(c0.y, v0.y, s1);
        s1 = fmaf(c0.z, v0.z, s1); s1 = fmaf(c0.w, v0.w, s1);
        s1 = fmaf(c1.x, v1.x, s1); s1 = fmaf(c1.y, v1.y, s1);
        s1 = fmaf(c1.z, v1.z, s1); s1 = fmaf(c1.w, v1.w, s1);
#pragma unroll
        for (int off = 16; off > 0; off >>= 1) {
            s0 += __shfl_xor_sync(0xffffffffu, s0, off);
            s1 += __shfl_xor_sync(0xffffffffu, s1, off);
        }
        if (lane == 0) {
            out[base + m]     = s0;
            out[base + m + 8] = s1;
        }
    }
    if (m < mend) {
        float4 a0 = xb[(size_t)m * 64 + lane];
        float4 a1 = xb[(size_t)m * 64 + 32 + lane];
        float s0 = 0.f;
        s0 = fmaf(a0.x, v0.x, s0); s0 = fmaf(a0.y, v0.y, s0);
        s0 = fmaf(a0.z, v0.z, s0); s0 = fmaf(a0.w, v0.w, s0);
        s0 = fmaf(a1.x, v1.x, s0); s0 = fmaf(a1.y, v1.y, s0);
        s0 = fmaf(a1.z, v1.z, s0); s0 = fmaf(a1.w, v1.w, s0);
#pragma unroll
        for (int off = 16; off > 0; off >>= 1)
            s0 += __shfl_xor_sync(0xffffffffu, s0, off);
        if (lane == 0) out[base + m] = s0;
    }
}

extern "C" void kernel_launch(void* const* d_in, const int* in_sizes, int n_in,
                              void* d_out, int out_size) {
    const float* xss  = (const float*)d_in[0];
    const float* Wk   = (const float*)d_in[1];
    const float* Wc   = (const float*)d_in[2];
    const float* proj = (const float*)d_in[3];
    const int*   seq  = (const int*)d_in[4];
    float* out = (float*)d_out;

    setup_kernel<<<DIM_Q + 1, 256>>>(Wk, Wc, proj, seq);
    xsum_kernel<<<DIM_B, 256>>>(xss, seq);
    vgemm_kernel<<<128, 512>>>();
    y_kernel<<<2 * DIM_B, 256>>>(xss, seq, out);
}